// round 10
// baseline (speedup 1.0000x reference)
#include <cuda_runtime.h>

#define T     4096
#define TQ    1024         // float4s per array
#define NTH   160
#define CHUNK 1024
#define W2    140          // pair-row width; W2 % 8 == 4 -> staging conflict-free
#define BUFP  (4 * W2)     // 560 pairs per buffer (4480 B)
#define NSTG  280          // float4s staged per array (pairs 0..559)

typedef unsigned long long u64;

// db4 synthesis filters pre-scaled by 0.5 (the per-level factor)
#define L0c ( 0.5f *  0.23037781330885523f)
#define L1c ( 0.5f *  0.7148465705525415f)
#define L2c ( 0.5f *  0.6308807679295904f)
#define L3c ( 0.5f * -0.02798376941698385f)
#define L4c ( 0.5f * -0.18703481171888114f)
#define L5c ( 0.5f *  0.030841381835986965f)
#define L6c ( 0.5f *  0.032883011666982945f)
#define L7c ( 0.5f * -0.010597401784997278f)
// rec_hi[k] = (-1)^k * rec_lo[7-k]
#define H0c ( L7c)
#define H1c (-L6c)
#define H2c ( L5c)
#define H3c (-L4c)
#define H4c ( L3c)
#define H5c (-L2c)
#define H6c ( L1c)
#define H7c (-L0c)

// 4-row pair-transposed layout: pair p at phys64 = (p & 3)*W2 + (p >> 2).
// Thread pair-base is 4t, so (4t+q)&3 = q&3 and (4t+q)>>2 = t + (q>>2):
// every window access is LDS.64 [Rbase + imm], lanes consecutive -> conflict-free.

// Direct stage: global float4 -> shared pairs 2idx, 2idx+1.
__device__ __forceinline__ void stage(u64* __restrict__ s,
                                      const float4* __restrict__ g4,
                                      int f4base, int tid) {
#pragma unroll
    for (int i = 0; i < 2; ++i) {
        int idx = tid + i * NTH;
        if (idx < NSTG) {
            float4 v = __ldg(&g4[(f4base + idx) & (TQ - 1)]);
            int r = 2 * (idx & 1);           // (2idx) & 3
            int q = idx >> 1;                // (2idx) >> 2
            *(float2*)(s + (r + 0) * W2 + q) = make_float2(v.x, v.y);
            *(float2*)(s + (r + 1) * W2 + q) = make_float2(v.z, v.w);
        }
    }
}

struct Pref2 { float4 v[2]; };

__device__ __forceinline__ void prefetch(Pref2& p, const float4* __restrict__ g4,
                                         int f4base, int tid) {
#pragma unroll
    for (int i = 0; i < 2; ++i) {
        int idx = tid + i * NTH;
        p.v[i] = (idx < NSTG) ? __ldg(&g4[(f4base + idx) & (TQ - 1)])
                              : make_float4(0.f, 0.f, 0.f, 0.f);
    }
}

__device__ __forceinline__ void commit(u64* __restrict__ s, const Pref2& p, int tid) {
#pragma unroll
    for (int i = 0; i < 2; ++i) {
        int idx = tid + i * NTH;
        if (idx < NSTG) {
            int r = 2 * (idx & 1);
            int q = idx >> 1;
            *(float2*)(s + (r + 0) * W2 + q) = make_float2(p.v[i].x, p.v[i].y);
            *(float2*)(s + (r + 1) * W2 + q) = make_float2(p.v[i].z, p.v[i].w);
        }
    }
}

// Scalar pass, dilation D.  Thread t produces 8 samples at buffer-local
// 8t + OFF + j (j = 0..7).  Tap m reads local li = 8t + OFF + j + D*(3-m).
// Stream pairs q (samples 8t+2q, 8t+2q+1):  j = 2q (+1) - OFF - D*(3-m).
// All coefficient multiplies are FFMA-imm (rt=1, zero coefficient regs).
template <int D, int OFF, int QMIN, int QMAX>
__device__ __forceinline__ void pass_scalar(const u64* __restrict__ buf,
                                            float* acc, const float* cf, int t) {
    const u64* p = buf + t;
#pragma unroll
    for (int q = QMIN; q <= QMAX; ++q) {
        u64 vv = p[(q & 3) * W2 + (q >> 2)];
        float2 v = *(float2*)&vv;
#pragma unroll
        for (int m = 0; m < 8; ++m) {
            {   const int j = 2 * q     - OFF - D * (3 - m);
                if (j >= 0 && j < 8) acc[j] = fmaf(cf[m], v.x, acc[j]); }
            {   const int j = 2 * q + 1 - OFF - D * (3 - m);
                if (j >= 0 && j < 8) acc[j] = fmaf(cf[m], v.y, acc[j]); }
        }
    }
}

__device__ __forceinline__ void store_level(u64* __restrict__ s,
                                            const float* acc, int t) {
    u64* p = s + t;                          // pairs 4t+k -> phys k*W2 + t
#pragma unroll
    for (int k = 0; k < 4; ++k)
        *(float2*)(p + k * W2) = make_float2(acc[2 * k], acc[2 * k + 1]);
}

__global__ void __launch_bounds__(NTH, 10)
iswt_kernel(const float* __restrict__ x, float* __restrict__ out) {
    __shared__ u64 bA[BUFP];   // cA3, then cD1
    __shared__ u64 bB[BUFP];   // cD3, then R2
    __shared__ u64 bC[BUFP];   // cD2
    __shared__ u64 bD[BUFP];   // R1

    const int bn  = blockIdx.x >> 2;           // row in [0, 2048)
    const int S   = (blockIdx.x & 3) << 10;    // chunk start: 0/1024/2048/3072
    const int tid = threadIdx.x;
    const float* g = x + (size_t)bn * 4 * T;   // cA3 | cD3 | cD2 | cD1
    const float4* g4 = (const float4*)g;

    const int o32 = (S - 32) >> 2;             // buffer origins (float4 index)
    const int o16 = (S - 16) >> 2;
    const int o8  = (S - 8)  >> 2;

    stage(bA, g4 + 0 * TQ, o32, tid);          // cA3  (origin S-32)
    stage(bB, g4 + 1 * TQ, o32, tid);          // cD3  (origin S-32)
    stage(bC, g4 + 2 * TQ, o16, tid);          // cD2  (origin S-16)
    Pref2 pE; prefetch(pE, g4 + 3 * TQ, o8, tid);   // cD1 -> regs (in flight)
    __syncthreads();

    const float CFL[8] = {L0c,L1c,L2c,L3c,L4c,L5c,L6c,L7c};
    const float CFH[8] = {H0c,H1c,H2c,H3c,H4c,H5c,H6c,H7c};

    // Level 1 (d=4, OFF=16): cA3,cD3 -> R1 (origin S-16), 132 threads
    if (tid < 132) {
        float acc[8];
#pragma unroll
        for (int j = 0; j < 8; ++j) acc[j] = 0.0f;
        pass_scalar<4, 16, 0, 17>(bA, acc, CFL, tid);
        pass_scalar<4, 16, 0, 17>(bB, acc, CFH, tid);
        store_level(bD, acc, tid);
    }
    __syncthreads();

    // cA3 dead -> commit cD1 (origin S-8) into bA; data long arrived.
    commit(bA, pE, tid);

    // Level 2 (d=2, OFF=8): R1,cD2 -> R2 (origin S-8) into bB, 130 threads
    if (tid < 130) {
        float acc[8];
#pragma unroll
        for (int j = 0; j < 8; ++j) acc[j] = 0.0f;
        pass_scalar<2, 8, 0, 10>(bD, acc, CFL, tid);
        pass_scalar<2, 8, 0, 10>(bC, acc, CFH, tid);
        store_level(bB, acc, tid);
    }
    __syncthreads();

    // Level 3 (d=1, OFF=8): R2,cD1 -> global [S+8t, S+8t+8), 128 threads
    if (tid < 128) {
        float acc[8];
#pragma unroll
        for (int j = 0; j < 8; ++j) acc[j] = 0.0f;
        pass_scalar<1, 8, 2, 9>(bB, acc, CFL, tid);
        pass_scalar<1, 8, 2, 9>(bA, acc, CFH, tid);
        float4* o = (float4*)(out + (size_t)bn * T + S + tid * 8);
        o[0] = make_float4(acc[0], acc[1], acc[2], acc[3]);
        o[1] = make_float4(acc[4], acc[5], acc[6], acc[7]);
    }
}

extern "C" void kernel_launch(void* const* d_in, const int* in_sizes, int n_in,
                              void* d_out, int out_size) {
    const float* x = (const float*)d_in[0];
    float* out = (float*)d_out;
    iswt_kernel<<<8192, NTH>>>(x, out);
}

// round 11
// speedup vs baseline: 1.1615x; 1.1615x over previous
#include <cuda_runtime.h>

#define T     4096
#define TQ    1024         // float4s per array
#define NTH   160
#define W2    140          // pair-row width; W2 % 8 == 4 -> staging conflict-free
#define BUFP  (4 * W2)     // 560 pairs per buffer (4480 B)
#define NSTG  280          // float4s staged per array (pairs 0..559)

typedef unsigned long long u64;

// db4 synthesis filters pre-scaled by 0.5 (the per-level factor)
#define L0c ( 0.5f *  0.23037781330885523f)
#define L1c ( 0.5f *  0.7148465705525415f)
#define L2c ( 0.5f *  0.6308807679295904f)
#define L3c ( 0.5f * -0.02798376941698385f)
#define L4c ( 0.5f * -0.18703481171888114f)
#define L5c ( 0.5f *  0.030841381835986965f)
#define L6c ( 0.5f *  0.032883011666982945f)
#define L7c ( 0.5f * -0.010597401784997278f)
// rec_hi[k] = (-1)^k * rec_lo[7-k]
#define H0c ( L7c)
#define H1c (-L6c)
#define H2c ( L5c)
#define H3c (-L4c)
#define H4c ( L3c)
#define H5c (-L2c)
#define H6c ( L1c)
#define H7c (-L0c)

// Packed (x == y) coefficient pairs for FFMA2 (loaded as LDC.64)
__constant__ float2 CL2[8] = {
    {L0c,L0c},{L1c,L1c},{L2c,L2c},{L3c,L3c},{L4c,L4c},{L5c,L5c},{L6c,L6c},{L7c,L7c}};
__constant__ float2 CH2[8] = {
    {H0c,H0c},{H1c,H1c},{H2c,H2c},{H3c,H3c},{H4c,H4c},{H5c,H5c},{H6c,H6c},{H7c,H7c}};

__device__ __forceinline__ void fma2(u64& d, u64 c, u64 v) {
    asm("fma.rn.f32x2 %0, %1, %2, %0;" : "+l"(d) : "l"(c), "l"(v));
}

// 4-row pair-transposed layout: pair p at phys64 = (p & 3)*W2 + (p >> 2).
// Thread pair-base is 4t, so window accesses are LDS.64 [Rbase + imm],
// lanes consecutive -> conflict-free.

__device__ __forceinline__ void stage(u64* __restrict__ s,
                                      const float4* __restrict__ g4,
                                      int f4base, int tid) {
#pragma unroll
    for (int i = 0; i < 2; ++i) {
        int idx = tid + i * NTH;
        if (idx < NSTG) {
            float4 v = __ldg(&g4[(f4base + idx) & (TQ - 1)]);
            int r = 2 * (idx & 1);           // (2idx) & 3
            int q = idx >> 1;                // (2idx) >> 2
            *(float2*)(s + (r + 0) * W2 + q) = make_float2(v.x, v.y);
            *(float2*)(s + (r + 1) * W2 + q) = make_float2(v.z, v.w);
        }
    }
}

struct Pref2 { float4 v[2]; };

__device__ __forceinline__ void prefetch(Pref2& p, const float4* __restrict__ g4,
                                         int f4base, int tid) {
#pragma unroll
    for (int i = 0; i < 2; ++i) {
        int idx = tid + i * NTH;
        p.v[i] = (idx < NSTG) ? __ldg(&g4[(f4base + idx) & (TQ - 1)])
                              : make_float4(0.f, 0.f, 0.f, 0.f);
    }
}

__device__ __forceinline__ void commit(u64* __restrict__ s, const Pref2& p, int tid) {
#pragma unroll
    for (int i = 0; i < 2; ++i) {
        int idx = tid + i * NTH;
        if (idx < NSTG) {
            int r = 2 * (idx & 1);
            int q = idx >> 1;
            *(float2*)(s + (r + 0) * W2 + q) = make_float2(p.v[i].x, p.v[i].y);
            *(float2*)(s + (r + 1) * W2 + q) = make_float2(p.v[i].z, p.v[i].w);
        }
    }
}

// Even-dilation FFMA2 pass: acc pair kk (samples 2kk,2kk+1 of the octet at
// 8t+OFF) gets tap m from pair q = kk + (D*(3-m)+OFF)/2 (all shifts even).
template <int D, int OFF, int QMAX>
__device__ __forceinline__ void pass_even2(const u64* __restrict__ buf, u64* acc,
                                           const float2* __restrict__ coef, int t) {
    u64 c[8];
    const u64* cu = (const u64*)coef;        // LDC.64
#pragma unroll
    for (int m = 0; m < 8; ++m) c[m] = cu[m];
    const u64* p = buf + t;
#pragma unroll
    for (int q = 0; q <= QMAX; ++q) {
        u64 v = p[(q & 3) * W2 + (q >> 2)];
#pragma unroll
        for (int m = 0; m < 8; ++m) {
            const int kk = q - (D * (3 - m) + OFF) / 2;
            if (kk >= 0 && kk < 4) fma2(acc[kk], c[m], v);
        }
    }
}

// D=1 scalar pass (OFF=8): octet j = 2q(+1) - 8 - (3-m); FFMA-imm.
template <int D, int OFF, int QMIN, int QMAX>
__device__ __forceinline__ void pass_scalar(const u64* __restrict__ buf,
                                            float* acc, const float* cf, int t) {
    const u64* p = buf + t;
#pragma unroll
    for (int q = QMIN; q <= QMAX; ++q) {
        u64 vv = p[(q & 3) * W2 + (q >> 2)];
        float2 v = *(float2*)&vv;
#pragma unroll
        for (int m = 0; m < 8; ++m) {
            {   const int j = 2 * q     - OFF - D * (3 - m);
                if (j >= 0 && j < 8) acc[j] = fmaf(cf[m], v.x, acc[j]); }
            {   const int j = 2 * q + 1 - OFF - D * (3 - m);
                if (j >= 0 && j < 8) acc[j] = fmaf(cf[m], v.y, acc[j]); }
        }
    }
}

__global__ void __launch_bounds__(NTH, 9)
iswt_kernel(const float* __restrict__ x, float* __restrict__ out) {
    __shared__ u64 bA[BUFP];   // cA3, then cD1
    __shared__ u64 bB[BUFP];   // cD3, then R2
    __shared__ u64 bC[BUFP];   // cD2
    __shared__ u64 bD[BUFP];   // R1

    const int bn  = blockIdx.x >> 2;           // row in [0, 2048)
    const int S   = (blockIdx.x & 3) << 10;    // chunk start: 0/1024/2048/3072
    const int tid = threadIdx.x;
    const float* g = x + (size_t)bn * 4 * T;   // cA3 | cD3 | cD2 | cD1
    const float4* g4 = (const float4*)g;

    const int o32 = (S - 32) >> 2;             // buffer origins (float4 index)
    const int o16 = (S - 16) >> 2;
    const int o8  = (S - 8)  >> 2;

    stage(bA, g4 + 0 * TQ, o32, tid);          // cA3  (origin S-32)
    stage(bB, g4 + 1 * TQ, o32, tid);          // cD3  (origin S-32)
    stage(bC, g4 + 2 * TQ, o16, tid);          // cD2  (origin S-16)
    Pref2 pE; prefetch(pE, g4 + 3 * TQ, o8, tid);   // cD1 -> regs (in flight)
    __syncthreads();

    // Level 1 (d=4, OFF=16): cA3,cD3 -> R1 (origin S-16), 132 threads, FFMA2
    if (tid < 132) {
        u64 acc[4];
#pragma unroll
        for (int k = 0; k < 4; ++k) acc[k] = 0ULL;
        pass_even2<4, 16, 17>(bA, acc, CL2, tid);
        pass_even2<4, 16, 17>(bB, acc, CH2, tid);
        u64* p = bD + tid;
#pragma unroll
        for (int k = 0; k < 4; ++k) p[k * W2] = acc[k];
    }
    __syncthreads();

    // cA3 dead -> commit cD1 (origin S-8) into bA; data long arrived.
    commit(bA, pE, tid);

    // Level 2 (d=2, OFF=8): R1,cD2 -> R2 (origin S-8) into bB, 130 threads, FFMA2
    if (tid < 130) {
        u64 acc[4];
#pragma unroll
        for (int k = 0; k < 4; ++k) acc[k] = 0ULL;
        pass_even2<2, 8, 10>(bD, acc, CL2, tid);
        pass_even2<2, 8, 10>(bC, acc, CH2, tid);
        u64* p = bB + tid;
#pragma unroll
        for (int k = 0; k < 4; ++k) p[k * W2] = acc[k];
    }
    __syncthreads();

    // Level 3 (d=1, OFF=8): R2,cD1 -> global [S+8t, S+8t+8), scalar FFMA-imm
    if (tid < 128) {
        const float CFL[8] = {L0c,L1c,L2c,L3c,L4c,L5c,L6c,L7c};
        const float CFH[8] = {H0c,H1c,H2c,H3c,H4c,H5c,H6c,H7c};
        float acc[8];
#pragma unroll
        for (int j = 0; j < 8; ++j) acc[j] = 0.0f;
        pass_scalar<1, 8, 2, 9>(bB, acc, CFL, tid);
        pass_scalar<1, 8, 2, 9>(bA, acc, CFH, tid);
        float4* o = (float4*)(out + (size_t)bn * T + S + tid * 8);
        o[0] = make_float4(acc[0], acc[1], acc[2], acc[3]);
        o[1] = make_float4(acc[4], acc[5], acc[6], acc[7]);
    }
}

extern "C" void kernel_launch(void* const* d_in, const int* in_sizes, int n_in,
                              void* d_out, int out_size) {
    const float* x = (const float*)d_in[0];
    float* out = (float*)d_out;
    iswt_kernel<<<8192, NTH>>>(x, out);
}